// round 13
// baseline (speedup 1.0000x reference)
#include <cuda_runtime.h>
#include <cuda_bf16.h>

#define FULL 0xffffffffu
#define MAXB 4096
#define FDIM 168   // [0:32) accp | [32:64) accc | [64:165) counts | pad

// ---- device scratch (static: no allocation anywhere) ----
__device__ float g_accum[MAXB * FDIM];
__device__ float g_G[FDIM * 64];     // folded weight matrix
__device__ float g_b1[64];           // folded fc1 bias

// ============================================================
// Fold work (runs in kA's LEADING blocks, wave 1, hidden under
// the chunk workload): G[168x64], b1[64].
// f layout: [0:32) u_p | [32:64) u_c | [64:115) cnt_p | [115:165) cnt_c
// ============================================================
__device__ void fold_work(int gid,
                          const float* __restrict__ w_p2, const float* __restrict__ b_p2,
                          const float* __restrict__ w_c2, const float* __restrict__ b_c2,
                          const float* __restrict__ emb_gender, const float* __restrict__ emb_korean,
                          const float* __restrict__ emb_primary, const float* __restrict__ emb_job,
                          const float* __restrict__ emb_rep, const float* __restrict__ emb_place,
                          const float* __restrict__ emb_add,
                          const float* __restrict__ w_fc1, const float* __restrict__ b_fc1)
{
    if (gid >= 169 * 64) return;
    const int v = gid >> 6;
    const int j = gid & 63;

    if (v < 32) {                 // u_p @ w_p2 through w_fc1 rows 64..95
        float s = 0.f;
        #pragma unroll
        for (int d = 0; d < 32; d++)
            s = fmaf(w_p2[v * 32 + d], w_fc1[(64 + d) * 64 + j], s);
        g_G[v * 64 + j] = s;
    } else if (v < 64) {          // u_c @ w_c2 through w_fc1 rows 96..127
        const int e = v - 32;
        float s = 0.f;
        #pragma unroll
        for (int d = 0; d < 32; d++)
            s = fmaf(w_c2[e * 32 + d], w_fc1[(96 + d) * 64 + j], s);
        g_G[v * 64 + j] = s;
    } else if (v < 115) {         // cat_p embedding rows through w_fc1 rows 0..31
        const int vv = v - 64;
        const float* er;
        if      (vv < 2)  er = emb_gender  + vv * 32;
        else if (vv < 4)  er = emb_korean  + (vv - 2) * 32;
        else if (vv < 6)  er = emb_primary + (vv - 4) * 32;
        else if (vv < 17) er = emb_job     + (vv - 6) * 32;
        else              er = emb_rep     + (vv - 17) * 32;
        float s = 0.f;
        #pragma unroll
        for (int d = 0; d < 32; d++)
            s = fmaf(er[d], w_fc1[d * 64 + j], s);
        g_G[v * 64 + j] = s;
    } else if (v < 165) {         // cat_c embedding rows through w_fc1 rows 32..63
        const int cc = v - 115;
        const float* er = (cc < 19) ? (emb_place + cc * 32) : (emb_add + (cc - 19) * 32);
        float s = 0.f;
        #pragma unroll
        for (int d = 0; d < 32; d++)
            s = fmaf(er[d], w_fc1[(32 + d) * 64 + j], s);
        g_G[v * 64 + j] = s;
    } else if (v < FDIM) {        // padding rows
        g_G[v * 64 + j] = 0.f;
    } else {                      // v == 168: folded bias
        float s = b_fc1[j];
        #pragma unroll
        for (int d = 0; d < 32; d++) {
            s = fmaf(b_p2[d], w_fc1[(64 + d) * 64 + j], s);
            s = fmaf(b_c2[d], w_fc1[(96 + d) * 64 + j], s);
        }
        g_b1[j] = s;
    }
}

// ============================================================
// kA: leading blocks fold; remaining blocks do one warp per
// (row, chunk) with RED.ADD into g_accum.
// Count layout (101): gender@0(2) korean@2(2) primary@4(2)
// job@6(11) rep@17(34) place@51(19) add@70(31)
// ============================================================
__device__ __forceinline__ void hupd_g(float* fr, int base, int idx, int lane) {
    unsigned m = __match_any_sync(FULL, idx);
    int leader = __ffs(m) - 1;
    if (lane == leader && idx != 999) {
        atomicAdd(fr + base + idx, (float)__popc(m));
    }
}

__global__ void __launch_bounds__(256)
ka_chunks(const float* __restrict__ cont_p, const float* __restrict__ cont_c,
          const int* __restrict__ cat_p, const int* __restrict__ cat_c,
          const int* __restrict__ lengths,
          const float* __restrict__ w_p1, const float* __restrict__ b_p1,
          const float* __restrict__ w_c1, const float* __restrict__ b_c1,
          const float* __restrict__ w_p2, const float* __restrict__ b_p2,
          const float* __restrict__ w_c2, const float* __restrict__ b_c2,
          const float* __restrict__ emb_gender, const float* __restrict__ emb_korean,
          const float* __restrict__ emb_primary, const float* __restrict__ emb_job,
          const float* __restrict__ emb_rep, const float* __restrict__ emb_place,
          const float* __restrict__ emb_add,
          const float* __restrict__ w_fc1, const float* __restrict__ b_fc1,
          int S, int B, int smax, int foldBlocks)
{
    __shared__ float4 stX[8][32];   // (p0, c0, p1, c1)
    __shared__ float2 stY[8][32];   // (p2, 0)

    // Leading blocks: fold (wave 1, hidden under the chunk workload).
    if (blockIdx.x < foldBlocks) {
        const int gid = blockIdx.x * 256 + threadIdx.x;
        fold_work(gid, w_p2, b_p2, w_c2, b_c2,
                  emb_gender, emb_korean, emb_primary, emb_job, emb_rep,
                  emb_place, emb_add, w_fc1, b_fc1);
        return;
    }

    const int lane = threadIdx.x & 31;
    const int wib  = threadIdx.x >> 5;
    const int g    = (blockIdx.x - foldBlocks) * 8 + wib;
    const int row  = g / smax;
    const int chunk = g - row * smax;
    if (row >= B) return;

    const int len = lengths[row];
    const int t0  = chunk * 32;
    if (t0 >= len) return;                           // dead chunk: fast exit

    const int nv = min(32, len - t0);
    const bool valid = lane < nv;
    const int rowbase = row * S;
    const int t = t0 + lane;

    float p0 = 0.f, p1 = 0.f, p2 = 0.f, c0 = 0.f, c1 = 0.f;
    int i0 = 999, i1 = 999, i2 = 999, i3 = 999, i4 = 999, j0 = 999, j1 = 999;
    if (valid) {
        const float* cp = cont_p + (rowbase + t) * 3;
        p0 = cp[0]; p1 = cp[1]; p2 = cp[2];
        float2 cc = *reinterpret_cast<const float2*>(cont_c + (rowbase + t) * 2);
        c0 = cc.x; c1 = cc.y;
        const int* ip = cat_p + (rowbase + t) * 5;
        i0 = ip[0]; i1 = ip[1]; i2 = ip[2]; i3 = ip[3]; i4 = ip[4];
        int2 jc = *reinterpret_cast<const int2*>(cat_c + (rowbase + t) * 2);
        j0 = jc.x; j1 = jc.y;
    }

    stX[wib][lane] = make_float4(p0, c0, p1, c1);
    stY[wib][lane] = make_float2(p2, 0.f);

    float* fr = g_accum + row * FDIM;

    hupd_g(fr, 64 +  0, i0, lane);
    hupd_g(fr, 64 +  2, i1, lane);
    hupd_g(fr, 64 +  4, i2, lane);
    hupd_g(fr, 64 +  6, i3, lane);
    hupd_g(fr, 64 + 17, i4, lane);
    hupd_g(fr, 64 + 51, j0, lane);
    hupd_g(fr, 64 + 70, j1, lane);

    const float wp0 = w_p1[lane];
    const float wp1 = w_p1[32 + lane];
    const float wp2 = w_p1[64 + lane];
    const float bp  = b_p1[lane];
    const float wc0 = w_c1[lane];
    const float wc1 = w_c1[32 + lane];
    const float bc  = b_c1[lane];

    __syncwarp();

    float ap0 = 0.f, ap1 = 0.f, ac0 = 0.f, ac1 = 0.f;
    int j = 0;
    #pragma unroll 4
    for (; j + 2 <= nv; j += 2) {
        const float4 xA = stX[wib][j];
        const float2 yA = stY[wib][j];
        const float4 xB = stX[wib][j + 1];
        const float2 yB = stY[wib][j + 1];
        ap0 += fmaxf(fmaf(yA.x, wp2, fmaf(xA.z, wp1, fmaf(xA.x, wp0, bp))), 0.f);
        ac0 += fmaxf(fmaf(xA.w, wc1, fmaf(xA.y, wc0, bc)), 0.f);
        ap1 += fmaxf(fmaf(yB.x, wp2, fmaf(xB.z, wp1, fmaf(xB.x, wp0, bp))), 0.f);
        ac1 += fmaxf(fmaf(xB.w, wc1, fmaf(xB.y, wc0, bc)), 0.f);
    }
    if (j < nv) {
        const float4 xA = stX[wib][j];
        const float2 yA = stY[wib][j];
        ap0 += fmaxf(fmaf(yA.x, wp2, fmaf(xA.z, wp1, fmaf(xA.x, wp0, bp))), 0.f);
        ac0 += fmaxf(fmaf(xA.w, wc1, fmaf(xA.y, wc0, bc)), 0.f);
    }

    atomicAdd(fr + lane,      ap0 + ap1);
    atomicAdd(fr + 32 + lane, ac0 + ac1);
}

// ============================================================
// kC: tiled GEMM epilogue. 32 rows/block, 512 threads (16 warps).
// Thread = 1 row x 4 cols. out = relu(relu(F@G+b1)@w_fc2+b_fc2).
// ============================================================
__global__ void __launch_bounds__(512)
kc_gemm(const int* __restrict__ lengths,
        const float* __restrict__ w_fc2, const float* __restrict__ b_fc2,
        float* __restrict__ out, int B)
{
    __shared__ float Fs[32][FDIM];   // 21504 B
    __shared__ float Gs[84][64];     // 21504 B (two-phase reuse)
    __shared__ float b1s[64];
    __shared__ float il_s[32];

    const int tid  = threadIdx.x;
    const int row0 = blockIdx.x * 32;

    if (tid < 32) {
        const int row = row0 + tid;
        il_s[tid] = (row < B) ? (1.0f / (float)lengths[row]) : 0.f;
    }
    if (tid >= 32 && tid < 96) b1s[tid - 32] = g_b1[tid - 32];
    __syncthreads();   // il_s ready for scaled F load

    // Load F tile with scale-on-load (invlen / invlen*0.2 / invlen*0.5).
    const float4* src = reinterpret_cast<const float4*>(g_accum + (size_t)row0 * FDIM);
    for (int idx = tid; idx < 32 * (FDIM / 4); idx += 512) {
        const int r   = idx / (FDIM / 4);
        const int kk4 = idx - r * (FDIM / 4);
        const int row = row0 + r;
        float4 v = make_float4(0.f, 0.f, 0.f, 0.f);
        if (row < B) v = src[idx];
        const float il = il_s[r];
        const int kb = kk4 * 4;
        const float s0 = (kb + 0 < 64) ? il : ((kb + 0 < 115) ? il * 0.2f : il * 0.5f);
        const float s1 = (kb + 1 < 64) ? il : ((kb + 1 < 115) ? il * 0.2f : il * 0.5f);
        const float s2 = (kb + 2 < 64) ? il : ((kb + 2 < 115) ? il * 0.2f : il * 0.5f);
        const float s3 = (kb + 3 < 64) ? il : ((kb + 3 < 115) ? il * 0.2f : il * 0.5f);
        Fs[r][kb + 0] = v.x * s0;
        Fs[r][kb + 1] = v.y * s1;
        Fs[r][kb + 2] = v.z * s2;
        Fs[r][kb + 3] = v.w * s3;
    }

    // Thread tile: 1 row x 4 cols.
    const int r    = tid >> 4;            // 0..31
    const int colg = tid & 15;            // cols j = colg*4 .. colg*4+3
    const int j0   = colg * 4;

    float a0 = 0.f, a1 = 0.f, a2 = 0.f, a3 = 0.f;

    #pragma unroll
    for (int ph = 0; ph < 2; ph++) {
        __syncthreads();   // ph0: Fs ready; ph1: prior Gs consumers done
        const float4* gsrc = reinterpret_cast<const float4*>(g_G + ph * 84 * 64);
        for (int idx = tid; idx < 84 * 16; idx += 512)
            reinterpret_cast<float4*>(&Gs[0][0])[idx] = gsrc[idx];
        __syncthreads();

        const int kof = ph * 84;
        #pragma unroll 7
        for (int kk = 0; kk < 84; kk++) {
            const float f = Fs[r][kof + kk];
            const float4 gv = *reinterpret_cast<const float4*>(&Gs[kk][j0]);
            a0 = fmaf(f, gv.x, a0);
            a1 = fmaf(f, gv.y, a1);
            a2 = fmaf(f, gv.z, a2);
            a3 = fmaf(f, gv.w, a3);
        }
    }

    // Bias + relu -> H.
    const float h0 = fmaxf(a0 + b1s[j0 + 0], 0.f);
    const float h1 = fmaxf(a1 + b1s[j0 + 1], 0.f);
    const float h2 = fmaxf(a2 + b1s[j0 + 2], 0.f);
    const float h3 = fmaxf(a3 + b1s[j0 + 3], 0.f);

    // fc2 partials: w_fc2 [64][2] row-major; this thread's 4 j's = 8 floats.
    const float4* w2 = reinterpret_cast<const float4*>(w_fc2 + colg * 8);
    const float4 w2a = w2[0];   // (j0o0, j0o1, j1o0, j1o1)
    const float4 w2b = w2[1];   // (j2o0, j2o1, j3o0, j3o1)
    float s0 = h0 * w2a.x + h1 * w2a.z + h2 * w2b.x + h3 * w2b.z;
    float s1 = h0 * w2a.y + h1 * w2a.w + h2 * w2b.y + h3 * w2b.w;

    // Reduce over the 16 col groups (lanes 0-15 within each half-warp).
    #pragma unroll
    for (int m = 1; m <= 8; m <<= 1) {
        s0 += __shfl_xor_sync(FULL, s0, m);
        s1 += __shfl_xor_sync(FULL, s1, m);
    }

    if (colg == 0) {
        const int row = row0 + r;
        if (row < B) {
            float2 o;
            o.x = fmaxf(s0 + b_fc2[0], 0.f);
            o.y = fmaxf(s1 + b_fc2[1], 0.f);
            reinterpret_cast<float2*>(out)[row] = o;
        }
    }
}

extern "C" void kernel_launch(void* const* d_in, const int* in_sizes, int n_in,
                              void* d_out, int out_size)
{
    const float* cont_p   = (const float*)d_in[0];
    const float* cont_c   = (const float*)d_in[1];
    const int*   cat_p    = (const int*)  d_in[2];
    const int*   cat_c    = (const int*)  d_in[3];
    const int*   lengths  = (const int*)  d_in[4];
    const float* w_p1     = (const float*)d_in[5];
    const float* b_p1     = (const float*)d_in[6];
    const float* w_p2     = (const float*)d_in[7];
    const float* b_p2     = (const float*)d_in[8];
    const float* w_c1     = (const float*)d_in[9];
    const float* b_c1     = (const float*)d_in[10];
    const float* w_c2     = (const float*)d_in[11];
    const float* b_c2     = (const float*)d_in[12];
    const float* emb_gender  = (const float*)d_in[13];
    const float* emb_korean  = (const float*)d_in[14];
    const float* emb_primary = (const float*)d_in[15];
    const float* emb_job     = (const float*)d_in[16];
    const float* emb_rep     = (const float*)d_in[17];
    const float* emb_place   = (const float*)d_in[18];
    const float* emb_add     = (const float*)d_in[19];
    const float* w_fc1    = (const float*)d_in[20];
    const float* b_fc1    = (const float*)d_in[21];
    const float* w_fc2    = (const float*)d_in[22];
    const float* b_fc2    = (const float*)d_in[23];
    float* out = (float*)d_out;

    const int B = in_sizes[4];                 // lengths: [B]
    const int S = in_sizes[0] / (B * 3);       // cont_p: [B,S,3]
    const int smax = (S + 31) / 32;            // chunks per row

    // Zero accumulators (graph-capturable async memset, no allocation).
    void* accum_ptr = nullptr;
    cudaGetSymbolAddress(&accum_ptr, g_accum);
    cudaMemsetAsync(accum_ptr, 0, (size_t)B * FDIM * sizeof(float));

    // kA: fold blocks first (hidden in wave 1), then chunk blocks.
    const int foldBlocks  = (169 * 64 + 255) / 256;   // 43
    const int chunkBlocks = (B * smax + 7) / 8;
    ka_chunks<<<foldBlocks + chunkBlocks, 256>>>(
        cont_p, cont_c, cat_p, cat_c, lengths,
        w_p1, b_p1, w_c1, b_c1,
        w_p2, b_p2, w_c2, b_c2,
        emb_gender, emb_korean, emb_primary, emb_job, emb_rep,
        emb_place, emb_add, w_fc1, b_fc1,
        S, B, smax, foldBlocks);

    // kC: tiled GEMM epilogue.
    kc_gemm<<<(B + 31) / 32, 512>>>(lengths, w_fc2, b_fc2, out, B);
}

// round 14
// speedup vs baseline: 1.1873x; 1.1873x over previous
#include <cuda_runtime.h>
#include <cuda_bf16.h>

#define FULL 0xffffffffu
#define MAXB 4096
#define FDIM 168   // [0:32) accp | [32:64) accc | [64:165) counts | pad
#define NBLK 444   // 3 per SM on 148+ SMs -- all resident (required for barrier)

// ---- device scratch (static: no allocation anywhere) ----
__device__ float g_accum[MAXB * FDIM];
__device__ float g_G[FDIM * 64];
__device__ float g_b1[64];
__device__ unsigned g_bar_count = 0u;
__device__ volatile unsigned g_bar_gen = 0u;   // monotonic across replays

// Sense-reversing grid barrier. All NBLK blocks are resident (occupancy
// guaranteed by __launch_bounds__(256,3) + 38.7KB smem), so no deadlock.
__device__ __forceinline__ void grid_sync() {
    __threadfence();              // make this thread's STG/atomics visible
    __syncthreads();
    if (threadIdx.x == 0) {
        const unsigned gen = g_bar_gen;
        if (atomicAdd(&g_bar_count, 1u) == (unsigned)NBLK - 1u) {
            g_bar_count = 0u;
            __threadfence();
            g_bar_gen = gen + 1u;
        } else {
            while (g_bar_gen == gen) { }
            __threadfence();
        }
    }
    __syncthreads();
}

// ============================================================
// Fold: G[168x64], b1[64] (verified in R11-R13).
// f layout: [0:32) u_p | [32:64) u_c | [64:115) cnt_p | [115:165) cnt_c
// ============================================================
__device__ void fold_work(int gid,
                          const float* __restrict__ w_p2, const float* __restrict__ b_p2,
                          const float* __restrict__ w_c2, const float* __restrict__ b_c2,
                          const float* __restrict__ emb_gender, const float* __restrict__ emb_korean,
                          const float* __restrict__ emb_primary, const float* __restrict__ emb_job,
                          const float* __restrict__ emb_rep, const float* __restrict__ emb_place,
                          const float* __restrict__ emb_add,
                          const float* __restrict__ w_fc1, const float* __restrict__ b_fc1)
{
    const int v = gid >> 6;
    const int j = gid & 63;

    if (v < 32) {
        float s = 0.f;
        #pragma unroll
        for (int d = 0; d < 32; d++)
            s = fmaf(w_p2[v * 32 + d], w_fc1[(64 + d) * 64 + j], s);
        g_G[v * 64 + j] = s;
    } else if (v < 64) {
        const int e = v - 32;
        float s = 0.f;
        #pragma unroll
        for (int d = 0; d < 32; d++)
            s = fmaf(w_c2[e * 32 + d], w_fc1[(96 + d) * 64 + j], s);
        g_G[v * 64 + j] = s;
    } else if (v < 115) {
        const int vv = v - 64;
        const float* er;
        if      (vv < 2)  er = emb_gender  + vv * 32;
        else if (vv < 4)  er = emb_korean  + (vv - 2) * 32;
        else if (vv < 6)  er = emb_primary + (vv - 4) * 32;
        else if (vv < 17) er = emb_job     + (vv - 6) * 32;
        else              er = emb_rep     + (vv - 17) * 32;
        float s = 0.f;
        #pragma unroll
        for (int d = 0; d < 32; d++)
            s = fmaf(er[d], w_fc1[d * 64 + j], s);
        g_G[v * 64 + j] = s;
    } else if (v < 165) {
        const int cc = v - 115;
        const float* er = (cc < 19) ? (emb_place + cc * 32) : (emb_add + (cc - 19) * 32);
        float s = 0.f;
        #pragma unroll
        for (int d = 0; d < 32; d++)
            s = fmaf(er[d], w_fc1[(32 + d) * 64 + j], s);
        g_G[v * 64 + j] = s;
    } else if (v < FDIM) {
        g_G[v * 64 + j] = 0.f;
    } else {                      // v == 168: folded bias
        float s = b_fc1[j];
        #pragma unroll
        for (int d = 0; d < 32; d++) {
            s = fmaf(b_p2[d], w_fc1[(64 + d) * 64 + j], s);
            s = fmaf(b_c2[d], w_fc1[(96 + d) * 64 + j], s);
        }
        g_b1[j] = s;
    }
}

__device__ __forceinline__ void hupd_g(float* fr, int base, int idx, int lane) {
    unsigned m = __match_any_sync(FULL, idx);
    int leader = __ffs(m) - 1;
    if (lane == leader && idx != 999) {
        atomicAdd(fr + base + idx, (float)__popc(m));
    }
}

// ============================================================
// Fused persistent kernel: zero+fold | barrier | chunks | barrier | GEMM
// ============================================================
__global__ void __launch_bounds__(256, 3)
fused_all(const float* __restrict__ cont_p, const float* __restrict__ cont_c,
          const int* __restrict__ cat_p, const int* __restrict__ cat_c,
          const int* __restrict__ lengths,
          const float* __restrict__ w_p1, const float* __restrict__ b_p1,
          const float* __restrict__ w_c1, const float* __restrict__ b_c1,
          const float* __restrict__ w_p2, const float* __restrict__ b_p2,
          const float* __restrict__ w_c2, const float* __restrict__ b_c2,
          const float* __restrict__ emb_gender, const float* __restrict__ emb_korean,
          const float* __restrict__ emb_primary, const float* __restrict__ emb_job,
          const float* __restrict__ emb_rep, const float* __restrict__ emb_place,
          const float* __restrict__ emb_add,
          const float* __restrict__ w_fc1, const float* __restrict__ b_fc1,
          const float* __restrict__ w_fc2, const float* __restrict__ b_fc2,
          float* __restrict__ out, int S, int B, int smax)
{
    __shared__ float4 stX[8][32];     // phase-1 stage (p0, c0, p1, c1)
    __shared__ float2 stY[8][32];     // phase-1 stage (p2, 0)
    __shared__ float  Gs[84 * 64];    // phase-2 G half (two-phase)
    __shared__ float  Fs[16 * FDIM];  // phase-2 F tile
    __shared__ float  b1s[64];
    __shared__ float  il_s[16];

    const int tid  = threadIdx.x;
    const int lane = tid & 31;
    const int wib  = tid >> 5;
    const int gtid = blockIdx.x * 256 + tid;
    const int nthreads = NBLK * 256;

    // ---------------- Phase 0: zero accumulators + fold ----------------
    {
        float4* a4 = reinterpret_cast<float4*>(g_accum);
        const int n4 = (B * FDIM) >> 2;
        for (int i = gtid; i < n4; i += nthreads)
            a4[i] = make_float4(0.f, 0.f, 0.f, 0.f);
        for (int gid = gtid; gid < 169 * 64; gid += nthreads)
            fold_work(gid, w_p2, b_p2, w_c2, b_c2,
                      emb_gender, emb_korean, emb_primary, emb_job, emb_rep,
                      emb_place, emb_add, w_fc1, b_fc1);
    }
    grid_sync();

    // ---------------- Phase 1: chunk-parallel accumulate ----------------
    {
        const float wp0 = w_p1[lane];
        const float wp1 = w_p1[32 + lane];
        const float wp2 = w_p1[64 + lane];
        const float bp  = b_p1[lane];
        const float wc0 = w_c1[lane];
        const float wc1 = w_c1[32 + lane];
        const float bc  = b_c1[lane];

        const int wGid   = blockIdx.x * 8 + wib;
        const int nWarps = NBLK * 8;
        const int nTasks = B * smax;

        for (int task = wGid; task < nTasks; task += nWarps) {
            const int row = task / smax;
            const int chunk = task - row * smax;
            const int len = lengths[row];
            const int t0  = chunk * 32;
            if (t0 >= len) continue;                 // dead chunk

            const int nv = min(32, len - t0);
            const bool valid = lane < nv;
            const int rowbase = row * S;
            const int t = t0 + lane;

            float p0 = 0.f, p1 = 0.f, p2 = 0.f, c0 = 0.f, c1 = 0.f;
            int i0 = 999, i1 = 999, i2 = 999, i3 = 999, i4 = 999, j0 = 999, j1 = 999;
            if (valid) {
                const float* cp = cont_p + (rowbase + t) * 3;
                p0 = cp[0]; p1 = cp[1]; p2 = cp[2];
                float2 cc = *reinterpret_cast<const float2*>(cont_c + (rowbase + t) * 2);
                c0 = cc.x; c1 = cc.y;
                const int* ip = cat_p + (rowbase + t) * 5;
                i0 = ip[0]; i1 = ip[1]; i2 = ip[2]; i3 = ip[3]; i4 = ip[4];
                int2 jc = *reinterpret_cast<const int2*>(cat_c + (rowbase + t) * 2);
                j0 = jc.x; j1 = jc.y;
            }

            stX[wib][lane] = make_float4(p0, c0, p1, c1);
            stY[wib][lane] = make_float2(p2, 0.f);

            float* fr = g_accum + row * FDIM;

            hupd_g(fr, 64 +  0, i0, lane);
            hupd_g(fr, 64 +  2, i1, lane);
            hupd_g(fr, 64 +  4, i2, lane);
            hupd_g(fr, 64 +  6, i3, lane);
            hupd_g(fr, 64 + 17, i4, lane);
            hupd_g(fr, 64 + 51, j0, lane);
            hupd_g(fr, 64 + 70, j1, lane);

            __syncwarp();

            float ap0 = 0.f, ap1 = 0.f, ac0 = 0.f, ac1 = 0.f;
            int j = 0;
            #pragma unroll 4
            for (; j + 2 <= nv; j += 2) {
                const float4 xA = stX[wib][j];
                const float2 yA = stY[wib][j];
                const float4 xB = stX[wib][j + 1];
                const float2 yB = stY[wib][j + 1];
                ap0 += fmaxf(fmaf(yA.x, wp2, fmaf(xA.z, wp1, fmaf(xA.x, wp0, bp))), 0.f);
                ac0 += fmaxf(fmaf(xA.w, wc1, fmaf(xA.y, wc0, bc)), 0.f);
                ap1 += fmaxf(fmaf(yB.x, wp2, fmaf(xB.z, wp1, fmaf(xB.x, wp0, bp))), 0.f);
                ac1 += fmaxf(fmaf(xB.w, wc1, fmaf(xB.y, wc0, bc)), 0.f);
            }
            if (j < nv) {
                const float4 xA = stX[wib][j];
                const float2 yA = stY[wib][j];
                ap0 += fmaxf(fmaf(yA.x, wp2, fmaf(xA.z, wp1, fmaf(xA.x, wp0, bp))), 0.f);
                ac0 += fmaxf(fmaf(xA.w, wc1, fmaf(xA.y, wc0, bc)), 0.f);
            }

            atomicAdd(fr + lane,      ap0 + ap1);
            atomicAdd(fr + 32 + lane, ac0 + ac1);
            __syncwarp();   // WAR on stage before next task's stores
        }
    }
    grid_sync();

    // ---------------- Phase 2: GEMM epilogue (16-row tiles) ----------------
    {
        const int nTiles = (B + 15) >> 4;
        for (int tile = blockIdx.x; tile < nTiles; tile += NBLK) {
            const int row0 = tile * 16;
            __syncthreads();   // protect smem reuse across tiles / phases

            if (tid < 16) {
                const int row = row0 + tid;
                il_s[tid] = (row < B) ? (1.0f / (float)lengths[row]) : 0.f;
            }
            if (tid >= 32 && tid < 96) b1s[tid - 32] = g_b1[tid - 32];
            __syncthreads();

            // F tile, scale-on-load: 16 rows x 42 float4.
            const float4* src = reinterpret_cast<const float4*>(
                g_accum + (size_t)row0 * FDIM);
            for (int idx = tid; idx < 16 * (FDIM / 4); idx += 256) {
                const int r   = idx / (FDIM / 4);
                const int kk4 = idx - r * (FDIM / 4);
                const int row = row0 + r;
                float4 v = make_float4(0.f, 0.f, 0.f, 0.f);
                if (row < B) v = src[idx];
                const float il = il_s[r];
                const int kb = kk4 * 4;
                const float s0 = (kb + 0 < 64) ? il : ((kb + 0 < 115) ? il * 0.2f : il * 0.5f);
                const float s1 = (kb + 1 < 64) ? il : ((kb + 1 < 115) ? il * 0.2f : il * 0.5f);
                const float s2 = (kb + 2 < 64) ? il : ((kb + 2 < 115) ? il * 0.2f : il * 0.5f);
                const float s3 = (kb + 3 < 64) ? il : ((kb + 3 < 115) ? il * 0.2f : il * 0.5f);
                Fs[r * FDIM + kb + 0] = v.x * s0;
                Fs[r * FDIM + kb + 1] = v.y * s1;
                Fs[r * FDIM + kb + 2] = v.z * s2;
                Fs[r * FDIM + kb + 3] = v.w * s3;
            }

            const int r    = tid >> 4;        // 0..15
            const int colg = tid & 15;
            const int j0   = colg * 4;

            float a0 = 0.f, a1 = 0.f, a2 = 0.f, a3 = 0.f;

            #pragma unroll
            for (int ph = 0; ph < 2; ph++) {
                __syncthreads();
                const float4* gsrc = reinterpret_cast<const float4*>(g_G + ph * 84 * 64);
                for (int idx = tid; idx < 84 * 16; idx += 256)
                    reinterpret_cast<float4*>(Gs)[idx] = gsrc[idx];
                __syncthreads();

                const int kof = ph * 84;
                #pragma unroll 7
                for (int kk = 0; kk < 84; kk++) {
                    const float f = Fs[r * FDIM + kof + kk];
                    const float4 gv = *reinterpret_cast<const float4*>(&Gs[kk * 64 + j0]);
                    a0 = fmaf(f, gv.x, a0);
                    a1 = fmaf(f, gv.y, a1);
                    a2 = fmaf(f, gv.z, a2);
                    a3 = fmaf(f, gv.w, a3);
                }
            }

            const float h0 = fmaxf(a0 + b1s[j0 + 0], 0.f);
            const float h1 = fmaxf(a1 + b1s[j0 + 1], 0.f);
            const float h2 = fmaxf(a2 + b1s[j0 + 2], 0.f);
            const float h3 = fmaxf(a3 + b1s[j0 + 3], 0.f);

            const float4* w2 = reinterpret_cast<const float4*>(w_fc2 + colg * 8);
            const float4 w2a = w2[0];
            const float4 w2b = w2[1];
            float s0 = h0 * w2a.x + h1 * w2a.z + h2 * w2b.x + h3 * w2b.z;
            float s1 = h0 * w2a.y + h1 * w2a.w + h2 * w2b.y + h3 * w2b.w;

            #pragma unroll
            for (int m = 1; m <= 8; m <<= 1) {
                s0 += __shfl_xor_sync(FULL, s0, m);
                s1 += __shfl_xor_sync(FULL, s1, m);
            }

            if (colg == 0) {
                const int row = row0 + r;
                if (row < B) {
                    float2 o;
                    o.x = fmaxf(s0 + b_fc2[0], 0.f);
                    o.y = fmaxf(s1 + b_fc2[1], 0.f);
                    reinterpret_cast<float2*>(out)[row] = o;
                }
            }
        }
    }
}

extern "C" void kernel_launch(void* const* d_in, const int* in_sizes, int n_in,
                              void* d_out, int out_size)
{
    const float* cont_p   = (const float*)d_in[0];
    const float* cont_c   = (const float*)d_in[1];
    const int*   cat_p    = (const int*)  d_in[2];
    const int*   cat_c    = (const int*)  d_in[3];
    const int*   lengths  = (const int*)  d_in[4];
    const float* w_p1     = (const float*)d_in[5];
    const float* b_p1     = (const float*)d_in[6];
    const float* w_p2     = (const float*)d_in[7];
    const float* b_p2     = (const float*)d_in[8];
    const float* w_c1     = (const float*)d_in[9];
    const float* b_c1     = (const float*)d_in[10];
    const float* w_c2     = (const float*)d_in[11];
    const float* b_c2     = (const float*)d_in[12];
    const float* emb_gender  = (const float*)d_in[13];
    const float* emb_korean  = (const float*)d_in[14];
    const float* emb_primary = (const float*)d_in[15];
    const float* emb_job     = (const float*)d_in[16];
    const float* emb_rep     = (const float*)d_in[17];
    const float* emb_place   = (const float*)d_in[18];
    const float* emb_add     = (const float*)d_in[19];
    const float* w_fc1    = (const float*)d_in[20];
    const float* b_fc1    = (const float*)d_in[21];
    const float* w_fc2    = (const float*)d_in[22];
    const float* b_fc2    = (const float*)d_in[23];
    float* out = (float*)d_out;

    const int B = in_sizes[4];                 // lengths: [B]
    const int S = in_sizes[0] / (B * 3);       // cont_p: [B,S,3]
    const int smax = (S + 31) / 32;

    fused_all<<<NBLK, 256>>>(cont_p, cont_c, cat_p, cat_c, lengths,
                             w_p1, b_p1, w_c1, b_c1,
                             w_p2, b_p2, w_c2, b_c2,
                             emb_gender, emb_korean, emb_primary, emb_job,
                             emb_rep, emb_place, emb_add,
                             w_fc1, b_fc1, w_fc2, b_fc2,
                             out, S, B, smax);
}

// round 16
// speedup vs baseline: 1.4701x; 1.2382x over previous
#include <cuda_runtime.h>
#include <cuda_bf16.h>

#define FULL 0xffffffffu
#define MAXB 4096
#define FDIM 168   // [0:32) accp | [32:64) accc | [64:165) counts | pad

// ---- device scratch (static: no allocation anywhere) ----
__device__ float g_accum[MAXB * FDIM];
__device__ float g_G[FDIM * 64];     // folded weight matrix
__device__ float g_b1[64];           // folded fc1 bias

// ============================================================
// Fold (validated R7/R11/R12): G[168x64], b1[64].
// f layout: [0:32) u_p | [32:64) u_c | [64:115) cnt_p | [115:165) cnt_c
// ============================================================
__device__ void fold_work(int gid,
                          const float* __restrict__ w_p2, const float* __restrict__ b_p2,
                          const float* __restrict__ w_c2, const float* __restrict__ b_c2,
                          const float* __restrict__ emb_gender, const float* __restrict__ emb_korean,
                          const float* __restrict__ emb_primary, const float* __restrict__ emb_job,
                          const float* __restrict__ emb_rep, const float* __restrict__ emb_place,
                          const float* __restrict__ emb_add,
                          const float* __restrict__ w_fc1, const float* __restrict__ b_fc1)
{
    if (gid >= 169 * 64) return;
    const int v = gid >> 6;
    const int j = gid & 63;

    if (v < 32) {
        float s = 0.f;
        #pragma unroll
        for (int d = 0; d < 32; d++)
            s = fmaf(w_p2[v * 32 + d], w_fc1[(64 + d) * 64 + j], s);
        g_G[v * 64 + j] = s;
    } else if (v < 64) {
        const int e = v - 32;
        float s = 0.f;
        #pragma unroll
        for (int d = 0; d < 32; d++)
            s = fmaf(w_c2[e * 32 + d], w_fc1[(96 + d) * 64 + j], s);
        g_G[v * 64 + j] = s;
    } else if (v < 115) {
        const int vv = v - 64;
        const float* er;
        if      (vv < 2)  er = emb_gender  + vv * 32;
        else if (vv < 4)  er = emb_korean  + (vv - 2) * 32;
        else if (vv < 6)  er = emb_primary + (vv - 4) * 32;
        else if (vv < 17) er = emb_job     + (vv - 6) * 32;
        else              er = emb_rep     + (vv - 17) * 32;
        float s = 0.f;
        #pragma unroll
        for (int d = 0; d < 32; d++)
            s = fmaf(er[d], w_fc1[d * 64 + j], s);
        g_G[v * 64 + j] = s;
    } else if (v < 165) {
        const int cc = v - 115;
        const float* er = (cc < 19) ? (emb_place + cc * 32) : (emb_add + (cc - 19) * 32);
        float s = 0.f;
        #pragma unroll
        for (int d = 0; d < 32; d++)
            s = fmaf(er[d], w_fc1[(32 + d) * 64 + j], s);
        g_G[v * 64 + j] = s;
    } else if (v < FDIM) {
        g_G[v * 64 + j] = 0.f;
    } else {                      // v == 168: folded bias
        float s = b_fc1[j];
        #pragma unroll
        for (int d = 0; d < 32; d++) {
            s = fmaf(b_p2[d], w_fc1[(64 + d) * 64 + j], s);
            s = fmaf(b_c2[d], w_fc1[(96 + d) * 64 + j], s);
        }
        g_b1[j] = s;
    }
}

// ============================================================
// kA: 43 leading fold blocks (wave 1, hidden), then one warp
// per (row, chunk) with RED.ADD into g_accum.  (R10-proven.)
// Count layout (101): gender@0(2) korean@2(2) primary@4(2)
// job@6(11) rep@17(34) place@51(19) add@70(31)
// ============================================================
__device__ __forceinline__ void hupd_g(float* fr, int base, int idx, int lane) {
    unsigned m = __match_any_sync(FULL, idx);
    int leader = __ffs(m) - 1;
    if (lane == leader && idx != 999) {
        atomicAdd(fr + base + idx, (float)__popc(m));
    }
}

__global__ void __launch_bounds__(256)
ka_chunks(const float* __restrict__ cont_p, const float* __restrict__ cont_c,
          const int* __restrict__ cat_p, const int* __restrict__ cat_c,
          const int* __restrict__ lengths,
          const float* __restrict__ w_p1, const float* __restrict__ b_p1,
          const float* __restrict__ w_c1, const float* __restrict__ b_c1,
          const float* __restrict__ w_p2, const float* __restrict__ b_p2,
          const float* __restrict__ w_c2, const float* __restrict__ b_c2,
          const float* __restrict__ emb_gender, const float* __restrict__ emb_korean,
          const float* __restrict__ emb_primary, const float* __restrict__ emb_job,
          const float* __restrict__ emb_rep, const float* __restrict__ emb_place,
          const float* __restrict__ emb_add,
          const float* __restrict__ w_fc1, const float* __restrict__ b_fc1,
          int S, int B, int smax, int foldBlocks)
{
    __shared__ float4 stX[8][32];   // (p0, c0, p1, c1)
    __shared__ float2 stY[8][32];   // (p2, 0)

    if (blockIdx.x < foldBlocks) {
        fold_work(blockIdx.x * 256 + threadIdx.x, w_p2, b_p2, w_c2, b_c2,
                  emb_gender, emb_korean, emb_primary, emb_job, emb_rep,
                  emb_place, emb_add, w_fc1, b_fc1);
        return;
    }

    const int lane = threadIdx.x & 31;
    const int wib  = threadIdx.x >> 5;
    const int g    = (blockIdx.x - foldBlocks) * 8 + wib;
    const int row  = g / smax;
    const int chunk = g - row * smax;
    if (row >= B) return;

    const int len = lengths[row];
    const int t0  = chunk * 32;
    if (t0 >= len) return;                           // dead chunk: fast exit

    const int nv = min(32, len - t0);
    const bool valid = lane < nv;
    const int rowbase = row * S;
    const int t = t0 + lane;

    float p0 = 0.f, p1 = 0.f, p2 = 0.f, c0 = 0.f, c1 = 0.f;
    int i0 = 999, i1 = 999, i2 = 999, i3 = 999, i4 = 999, j0 = 999, j1 = 999;
    if (valid) {
        const float* cp = cont_p + (rowbase + t) * 3;
        p0 = cp[0]; p1 = cp[1]; p2 = cp[2];
        float2 cc = *reinterpret_cast<const float2*>(cont_c + (rowbase + t) * 2);
        c0 = cc.x; c1 = cc.y;
        const int* ip = cat_p + (rowbase + t) * 5;
        i0 = ip[0]; i1 = ip[1]; i2 = ip[2]; i3 = ip[3]; i4 = ip[4];
        int2 jc = *reinterpret_cast<const int2*>(cat_c + (rowbase + t) * 2);
        j0 = jc.x; j1 = jc.y;
    }

    stX[wib][lane] = make_float4(p0, c0, p1, c1);
    stY[wib][lane] = make_float2(p2, 0.f);

    float* fr = g_accum + row * FDIM;

    hupd_g(fr, 64 +  0, i0, lane);
    hupd_g(fr, 64 +  2, i1, lane);
    hupd_g(fr, 64 +  4, i2, lane);
    hupd_g(fr, 64 +  6, i3, lane);
    hupd_g(fr, 64 + 17, i4, lane);
    hupd_g(fr, 64 + 51, j0, lane);
    hupd_g(fr, 64 + 70, j1, lane);

    const float wp0 = w_p1[lane];
    const float wp1 = w_p1[32 + lane];
    const float wp2 = w_p1[64 + lane];
    const float bp  = b_p1[lane];
    const float wc0 = w_c1[lane];
    const float wc1 = w_c1[32 + lane];
    const float bc  = b_c1[lane];

    __syncwarp();

    float ap0 = 0.f, ap1 = 0.f, ac0 = 0.f, ac1 = 0.f;
    int j = 0;
    #pragma unroll 4
    for (; j + 2 <= nv; j += 2) {
        const float4 xA = stX[wib][j];
        const float2 yA = stY[wib][j];
        const float4 xB = stX[wib][j + 1];
        const float2 yB = stY[wib][j + 1];
        ap0 += fmaxf(fmaf(yA.x, wp2, fmaf(xA.z, wp1, fmaf(xA.x, wp0, bp))), 0.f);
        ac0 += fmaxf(fmaf(xA.w, wc1, fmaf(xA.y, wc0, bc)), 0.f);
        ap1 += fmaxf(fmaf(yB.x, wp2, fmaf(xB.z, wp1, fmaf(xB.x, wp0, bp))), 0.f);
        ac1 += fmaxf(fmaf(xB.w, wc1, fmaf(xB.y, wc0, bc)), 0.f);
    }
    if (j < nv) {
        const float4 xA = stX[wib][j];
        const float2 yA = stY[wib][j];
        ap0 += fmaxf(fmaf(yA.x, wp2, fmaf(xA.z, wp1, fmaf(xA.x, wp0, bp))), 0.f);
        ac0 += fmaxf(fmaf(xA.w, wc1, fmaf(xA.y, wc0, bc)), 0.f);
    }

    atomicAdd(fr + lane,      ap0 + ap1);
    atomicAdd(fr + 32 + lane, ac0 + ac1);
}

// ============================================================
// kD: epilogue GEMM, one WARP per row. 512 blocks x 256 thr
// (8 rows/block). Lane owns output pair (2*lane, 2*lane+1).
// Per k: 1 coalesced LDG.64 of G[k][0..63] per warp (L1-hot)
// + 1 LDS.64 broadcast of F[r][k..k+1]; 4 accumulators.
// fc2 = pure in-warp shfl reduction.
// ============================================================
__global__ void __launch_bounds__(256)
kd_gemm(const int* __restrict__ lengths,
        const float* __restrict__ w_fc2, const float* __restrict__ b_fc2,
        float* __restrict__ out, int B)
{
    __shared__ float Fs[8][FDIM];    // 5376 B, scaled F tile
    __shared__ float il_s[8];

    const int tid  = threadIdx.x;
    const int lane = tid & 31;
    const int r    = tid >> 5;       // warp index = row within tile
    const int row0 = blockIdx.x * 8;
    const int row  = row0 + r;

    if (tid < 8) {
        const int rw = row0 + tid;
        il_s[tid] = (rw < B) ? (1.0f / (float)lengths[rw]) : 0.f;
    }
    __syncthreads();

    // Load F tile with scale-on-load: 8 rows x 42 float4 = 336 float4.
    const float4* src = reinterpret_cast<const float4*>(g_accum + (size_t)row0 * FDIM);
    for (int idx = tid; idx < 8 * (FDIM / 4); idx += 256) {
        const int r2  = idx / (FDIM / 4);
        const int kk4 = idx - r2 * (FDIM / 4);
        const int rw  = row0 + r2;
        float4 v = make_float4(0.f, 0.f, 0.f, 0.f);
        if (rw < B) v = src[idx];
        const float il = il_s[r2];
        const int kb = kk4 * 4;
        const float s0 = (kb + 0 < 64) ? il : ((kb + 0 < 115) ? il * 0.2f : il * 0.5f);
        const float s1 = (kb + 1 < 64) ? il : ((kb + 1 < 115) ? il * 0.2f : il * 0.5f);
        const float s2 = (kb + 2 < 64) ? il : ((kb + 2 < 115) ? il * 0.2f : il * 0.5f);
        const float s3 = (kb + 3 < 64) ? il : ((kb + 3 < 115) ? il * 0.2f : il * 0.5f);
        Fs[r2][kb + 0] = v.x * s0;
        Fs[r2][kb + 1] = v.y * s1;
        Fs[r2][kb + 2] = v.z * s2;
        Fs[r2][kb + 3] = v.w * s3;
    }
    __syncthreads();

    const int j2 = lane * 2;        // this lane's two fc1 output columns
    float a0a = 0.f, a0b = 0.f, a1a = 0.f, a1b = 0.f;

    #pragma unroll 6
    for (int k = 0; k < FDIM; k += 2) {
        const float2 f01 = *reinterpret_cast<const float2*>(&Fs[r][k]);
        const float2 g0  = *reinterpret_cast<const float2*>(&g_G[k * 64 + j2]);
        const float2 g1  = *reinterpret_cast<const float2*>(&g_G[(k + 1) * 64 + j2]);
        a0a = fmaf(f01.x, g0.x, a0a);
        a1a = fmaf(f01.x, g0.y, a1a);
        a0b = fmaf(f01.y, g1.x, a0b);
        a1b = fmaf(f01.y, g1.y, a1b);
    }

    const float2 b1v = *reinterpret_cast<const float2*>(&g_b1[j2]);
    const float h0 = fmaxf(a0a + a0b + b1v.x, 0.f);
    const float h1 = fmaxf(a1a + a1b + b1v.y, 0.f);

    // fc2: w_fc2 [64][2] row-major; lane's 2 j's = 4 consecutive floats.
    const float4 w2 = *reinterpret_cast<const float4*>(w_fc2 + j2 * 2);
    float s0 = h0 * w2.x + h1 * w2.z;
    float s1 = h0 * w2.y + h1 * w2.w;

    #pragma unroll
    for (int m = 16; m; m >>= 1) {
        s0 += __shfl_xor_sync(FULL, s0, m);
        s1 += __shfl_xor_sync(FULL, s1, m);
    }

    if (lane == 0 && row < B) {
        float2 o;
        o.x = fmaxf(s0 + b_fc2[0], 0.f);
        o.y = fmaxf(s1 + b_fc2[1], 0.f);
        reinterpret_cast<float2*>(out)[row] = o;
    }
}

extern "C" void kernel_launch(void* const* d_in, const int* in_sizes, int n_in,
                              void* d_out, int out_size)
{
    const float* cont_p   = (const float*)d_in[0];
    const float* cont_c   = (const float*)d_in[1];
    const int*   cat_p    = (const int*)  d_in[2];
    const int*   cat_c    = (const int*)  d_in[3];
    const int*   lengths  = (const int*)  d_in[4];
    const float* w_p1     = (const float*)d_in[5];
    const float* b_p1     = (const float*)d_in[6];
    const float* w_p2     = (const float*)d_in[7];
    const float* b_p2     = (const float*)d_in[8];
    const float* w_c1     = (const float*)d_in[9];
    const float* b_c1     = (const float*)d_in[10];
    const float* w_c2     = (const float*)d_in[11];
    const float* b_c2     = (const float*)d_in[12];
    const float* emb_gender  = (const float*)d_in[13];
    const float* emb_korean  = (const float*)d_in[14];
    const float* emb_primary = (const float*)d_in[15];
    const float* emb_job     = (const float*)d_in[16];
    const float* emb_rep     = (const float*)d_in[17];
    const float* emb_place   = (const float*)d_in[18];
    const float* emb_add     = (const float*)d_in[19];
    const float* w_fc1    = (const float*)d_in[20];
    const float* b_fc1    = (const float*)d_in[21];
    const float* w_fc2    = (const float*)d_in[22];
    const float* b_fc2    = (const float*)d_in[23];
    float* out = (float*)d_out;

    const int B = in_sizes[4];                 // lengths: [B]
    const int S = in_sizes[0] / (B * 3);       // cont_p: [B,S,3]
    const int smax = (S + 31) / 32;

    // Zero accumulators (graph-capturable async memset, no allocation).
    void* accum_ptr = nullptr;
    cudaGetSymbolAddress(&accum_ptr, g_accum);
    cudaMemsetAsync(accum_ptr, 0, (size_t)B * FDIM * sizeof(float));

    // kA: fold blocks lead (wave 1), chunk blocks follow.
    const int foldBlocks  = (169 * 64 + 255) / 256;   // 43
    const int chunkBlocks = (B * smax + 7) / 8;
    ka_chunks<<<foldBlocks + chunkBlocks, 256>>>(
        cont_p, cont_c, cat_p, cat_c, lengths,
        w_p1, b_p1, w_c1, b_c1,
        w_p2, b_p2, w_c2, b_c2,
        emb_gender, emb_korean, emb_primary, emb_job, emb_rep,
        emb_place, emb_add, w_fc1, b_fc1,
        S, B, smax, foldBlocks);

    // kD: warp-per-row GEMM epilogue.
    kd_gemm<<<(B + 7) / 8, 256>>>(lengths, w_fc2, b_fc2, out, B);
}